// round 2
// baseline (speedup 1.0000x reference)
#include <cuda_runtime.h>
#include <cuda_bf16.h>
#include <math.h>

#define BB   8
#define SS   1043
#define NTOK 1024
#define NCLS 19
#define DM   768
#define NH   12
#define DH   64
#define DFF  3072
#define GSZ  32
#define IMG  512

// ---------------- scratch (device globals; allocation-free) ----------------
__device__ float g_X [BB*SS*DM];
__device__ float g_Hb[BB*SS*DM];
__device__ float g_Q [BB*NH*SS*DH];
__device__ float g_K [BB*NH*SS*DH];
__device__ float g_V [BB*NH*SS*DH];
__device__ float g_O [BB*SS*DM];
__device__ float g_FF[BB*SS*DFF];
__device__ float g_PA[BB*NTOK*DM];
__device__ float g_CL[BB*NCLS*DM];
__device__ float g_MS[BB*NCLS*GSZ*GSZ];

// ---------------- helpers ----------------
__device__ __forceinline__ float blockReduceSum(float v, float* red) {
    int tid = threadIdx.x;
    red[tid] = v; __syncthreads();
    for (int s = blockDim.x >> 1; s > 0; s >>= 1) {
        if (tid < s) red[tid] += red[tid + s];
        __syncthreads();
    }
    float r = red[0]; __syncthreads();
    return r;
}

// ---------------- generic SGEMM: C = act(A@B + bias) [+ resid] ----------------
// A: (M,K) row-major, B: (K,N) row-major, N % 128 == 0, K % 16 == 0.
// rpb/str: optional ragged row remap r -> (r/rpb)*str + r%rpb for A and C.
template<bool GELU>
__global__ void sgemm_k(const float* __restrict__ A, const float* __restrict__ Bw,
                        const float* __restrict__ bias, const float* __restrict__ resid,
                        float* __restrict__ C, int M, int N, int K,
                        int rpbA, int strA, int rpbC, int strC)
{
    __shared__ float As[16][132];
    __shared__ float Bs[16][132];
    int tid = threadIdx.x;
    int row0 = blockIdx.y * 128, col0 = blockIdx.x * 128;
    int ty = tid >> 4, tx = tid & 15;
    float acc[8][8];
#pragma unroll
    for (int i = 0; i < 8; i++)
#pragma unroll
        for (int j = 0; j < 8; j++) acc[i][j] = 0.f;

    for (int k0 = 0; k0 < K; k0 += 16) {
#pragma unroll
        for (int i = 0; i < 2; i++) {
            int f = tid * 2 + i;
            int r = f >> 2, c4 = f & 3;
            int gr = row0 + r;
            float4 v = make_float4(0.f, 0.f, 0.f, 0.f);
            if (gr < M) {
                size_t ar = rpbA ? (size_t)(gr / rpbA) * strA + (gr % rpbA) : (size_t)gr;
                v = *(const float4*)(A + ar * (size_t)K + k0 + c4 * 4);
            }
            As[c4*4+0][r] = v.x; As[c4*4+1][r] = v.y;
            As[c4*4+2][r] = v.z; As[c4*4+3][r] = v.w;
        }
#pragma unroll
        for (int i = 0; i < 2; i++) {
            int f = tid * 2 + i;
            int r = f >> 5, c = (f & 31) * 4;
            float4 v = *(const float4*)(Bw + (size_t)(k0 + r) * N + col0 + c);
            *(float4*)&Bs[r][c] = v;
        }
        __syncthreads();
#pragma unroll
        for (int k = 0; k < 16; k++) {
            float a[8], b[8];
            *(float4*)(a)     = *(float4*)&As[k][ty*8];
            *(float4*)(a + 4) = *(float4*)&As[k][ty*8+4];
            *(float4*)(b)     = *(float4*)&Bs[k][tx*8];
            *(float4*)(b + 4) = *(float4*)&Bs[k][tx*8+4];
#pragma unroll
            for (int i = 0; i < 8; i++)
#pragma unroll
                for (int j = 0; j < 8; j++) acc[i][j] = fmaf(a[i], b[j], acc[i][j]);
        }
        __syncthreads();
    }
#pragma unroll
    for (int i = 0; i < 8; i++) {
        int gr = row0 + ty * 8 + i;
        if (gr >= M) continue;
        size_t cr = rpbC ? (size_t)(gr / rpbC) * strC + (gr % rpbC) : (size_t)gr;
#pragma unroll
        for (int j = 0; j < 8; j++) {
            int gc = col0 + tx * 8 + j;
            float v = acc[i][j];
            if (bias) v += __ldg(&bias[gc]);
            if (GELU) v = 0.5f * v * (1.f + erff(v * 0.70710678118654752f));
            if (resid) v += resid[cr * (size_t)N + gc];
            C[cr * (size_t)N + gc] = v;
        }
    }
}

// ---------------- cls token append ----------------
__global__ void cls_copy_k(const float* __restrict__ cls_emb)
{
    int idx = blockIdx.x * 256 + threadIdx.x;
    if (idx >= BB * NCLS * DM) return;
    int b = idx / (NCLS * DM);
    int rem = idx % (NCLS * DM);
    g_X[((size_t)b * SS + NTOK) * DM + rem] = cls_emb[rem];
}

// ---------------- LayerNorm over DM ----------------
__global__ void ln_k(const float* __restrict__ in, const float* __restrict__ g,
                     const float* __restrict__ be, float* __restrict__ out)
{
    __shared__ float red[256];
    int tid = threadIdx.x;
    const float* p = in + (size_t)blockIdx.x * DM;
    float v0 = p[tid], v1 = p[tid + 256], v2 = p[tid + 512];
    float m = blockReduceSum(v0 + v1 + v2, red) * (1.f / 768.f);
    float d0 = v0 - m, d1 = v1 - m, d2 = v2 - m;
    float var = blockReduceSum(d0*d0 + d1*d1 + d2*d2, red) * (1.f / 768.f);
    float inv = rsqrtf(var + 1e-5f);
    float* o = out + (size_t)blockIdx.x * DM;
    o[tid]       = d0 * inv * g[tid]       + be[tid];
    o[tid + 256] = d1 * inv * g[tid + 256] + be[tid + 256];
    o[tid + 512] = d2 * inv * g[tid + 512] + be[tid + 512];
}

// ---------------- per-head QKV projection ----------------
__global__ void qkv_k(const float* __restrict__ qW, const float* __restrict__ qb,
                      const float* __restrict__ kW, const float* __restrict__ kb,
                      const float* __restrict__ vW, const float* __restrict__ vb,
                      int l)
{
    __shared__ float sW[64][64];
    __shared__ float sH[32][68];
    int b = blockIdx.z, h = blockIdx.y, s0 = blockIdx.x * 32;
    int tid = threadIdx.x;
#pragma unroll
    for (int i = 0; i < 2; i++) {
        int f = tid * 2 + i;
        int r = f >> 4, c = (f & 15) * 4;
        int s = s0 + r;
        float4 v = make_float4(0.f, 0.f, 0.f, 0.f);
        if (s < SS) v = *(const float4*)(g_Hb + ((size_t)b * SS + s) * DM + h * DH + c);
        *(float4*)&sH[r][c] = v;
    }
    const float* Ws[3] = {qW, kW, vW};
    const float* bsv[3] = {qb, kb, vb};
    float* Os[3] = {g_Q, g_K, g_V};
    int sl = tid >> 3;
    int e0 = (tid & 7) * 8;
    for (int m = 0; m < 3; m++) {
        __syncthreads();
        const float* W = Ws[m] + ((size_t)l * NH + h) * DH * DH;
#pragma unroll
        for (int i = 0; i < 4; i++) {
            int f = tid + i * 256;
            int r = f >> 4, c = (f & 15) * 4;
            *(float4*)&sW[r][c] = *(const float4*)(W + f * 4);
        }
        __syncthreads();
        float acc[8] = {0,0,0,0,0,0,0,0};
#pragma unroll
        for (int k = 0; k < 64; k++) {
            float hv = sH[sl][k];
            float4 w0 = *(float4*)&sW[k][e0];
            float4 w1 = *(float4*)&sW[k][e0 + 4];
            acc[0] = fmaf(hv, w0.x, acc[0]); acc[1] = fmaf(hv, w0.y, acc[1]);
            acc[2] = fmaf(hv, w0.z, acc[2]); acc[3] = fmaf(hv, w0.w, acc[3]);
            acc[4] = fmaf(hv, w1.x, acc[4]); acc[5] = fmaf(hv, w1.y, acc[5]);
            acc[6] = fmaf(hv, w1.z, acc[6]); acc[7] = fmaf(hv, w1.w, acc[7]);
        }
        int s = s0 + sl;
        if (s < SS) {
            const float* bbp = bsv[m] + ((size_t)l * NH + h) * DH;
            float* op = Os[m] + (((size_t)b * NH + h) * SS + s) * DH + e0;
#pragma unroll
            for (int j = 0; j < 8; j++) op[j] = acc[j] + bbp[e0 + j];
        }
    }
}

// ---------------- fused flash attention ----------------
// grid: (ceil(SS/64), BB*NH), block 256.
// Per block: 64 query rows of one (b,h). K/V tiles of 32 rows, online softmax.
__global__ void flash_attn_k()
{
    __shared__ float Qs[64][68];   // float4-aligned
    __shared__ float Ks[32][65];   // stride 65 -> conflict-free scalar reads
    __shared__ float Vs[32][68];   // float4-aligned reads
    __shared__ float Ps[64][36];

    int bh = blockIdx.y;
    int b = bh / NH, h = bh % NH;
    int q0 = blockIdx.x * 64;
    int tid = threadIdx.x;
    int ty = tid >> 4, tx = tid & 15;

    const float* Qb = g_Q + (size_t)bh * SS * DH;
    const float* Kb = g_K + (size_t)bh * SS * DH;
    const float* Vb = g_V + (size_t)bh * SS * DH;

    // load Q tile (64x64)
#pragma unroll
    for (int i = 0; i < 4; i++) {
        int f = tid + i * 256;
        int r = f >> 4, c = (f & 15) * 4;
        float4 v = make_float4(0.f,0.f,0.f,0.f);
        if (q0 + r < SS) v = *(const float4*)(Qb + (size_t)(q0 + r) * DH + c);
        *(float4*)&Qs[r][c] = v;
    }

    float m_r[4], l_r[4], o[4][4];
#pragma unroll
    for (int i = 0; i < 4; i++) {
        m_r[i] = -3.4e38f; l_r[i] = 0.f;
#pragma unroll
        for (int j = 0; j < 4; j++) o[i][j] = 0.f;
    }

    const int NKT = (SS + 31) / 32;   // 33
    for (int kt = 0; kt < NKT; kt++) {
        int k0 = kt * 32;
        // load K (scalar stores, stride 65) and V (float4) tiles
        __syncthreads();
#pragma unroll
        for (int i = 0; i < 2; i++) {
            int f = tid + i * 256;
            int r = f >> 4, c = (f & 15) * 4;
            float4 kv = make_float4(0.f,0.f,0.f,0.f);
            float4 vv = make_float4(0.f,0.f,0.f,0.f);
            if (k0 + r < SS) {
                kv = *(const float4*)(Kb + (size_t)(k0 + r) * DH + c);
                vv = *(const float4*)(Vb + (size_t)(k0 + r) * DH + c);
            }
            Ks[r][c] = kv.x; Ks[r][c+1] = kv.y; Ks[r][c+2] = kv.z; Ks[r][c+3] = kv.w;
            *(float4*)&Vs[r][c] = vv;
        }
        __syncthreads();

        // scores: s[i][j], rows q=ty*4+i, cols k=tx*2+j
        float s[4][2];
#pragma unroll
        for (int i = 0; i < 4; i++) { s[i][0] = 0.f; s[i][1] = 0.f; }
#pragma unroll 8
        for (int k = 0; k < 64; k++) {
            float b0 = Ks[tx*2][k], b1 = Ks[tx*2+1][k];
#pragma unroll
            for (int i = 0; i < 4; i++) {
                float a = Qs[ty*4+i][k];
                s[i][0] = fmaf(a, b0, s[i][0]);
                s[i][1] = fmaf(a, b1, s[i][1]);
            }
        }
        bool ok0 = (k0 + tx*2)     < SS;
        bool ok1 = (k0 + tx*2 + 1) < SS;
#pragma unroll
        for (int i = 0; i < 4; i++) {
            s[i][0] = ok0 ? s[i][0] * 0.125f : -3.4e38f;
            s[i][1] = ok1 ? s[i][1] * 0.125f : -3.4e38f;
        }

        // online softmax update (row reductions across 16 lanes)
        float p[4][2];
#pragma unroll
        for (int i = 0; i < 4; i++) {
            float mx = fmaxf(s[i][0], s[i][1]);
#pragma unroll
            for (int off = 8; off > 0; off >>= 1)
                mx = fmaxf(mx, __shfl_xor_sync(0xffffffffu, mx, off, 16));
            float newm = fmaxf(m_r[i], mx);
            float corr = __expf(m_r[i] - newm);
            p[i][0] = __expf(s[i][0] - newm);
            p[i][1] = __expf(s[i][1] - newm);
            float rs = p[i][0] + p[i][1];
#pragma unroll
            for (int off = 8; off > 0; off >>= 1)
                rs += __shfl_xor_sync(0xffffffffu, rs, off, 16);
            l_r[i] = l_r[i] * corr + rs;
            m_r[i] = newm;
#pragma unroll
            for (int j = 0; j < 4; j++) o[i][j] *= corr;
        }
        // stage P
#pragma unroll
        for (int i = 0; i < 4; i++) {
            Ps[ty*4+i][tx*2]   = p[i][0];
            Ps[ty*4+i][tx*2+1] = p[i][1];
        }
        __syncthreads();

        // O += P @ V  (o cols d = tx*4+j)
#pragma unroll 4
        for (int k = 0; k < 32; k++) {
            float4 vv = *(float4*)&Vs[k][tx*4];
#pragma unroll
            for (int i = 0; i < 4; i++) {
                float pv = Ps[ty*4+i][k];
                o[i][0] = fmaf(pv, vv.x, o[i][0]);
                o[i][1] = fmaf(pv, vv.y, o[i][1]);
                o[i][2] = fmaf(pv, vv.z, o[i][2]);
                o[i][3] = fmaf(pv, vv.w, o[i][3]);
            }
        }
    }

    // finalize
#pragma unroll
    for (int i = 0; i < 4; i++) {
        int q = q0 + ty*4 + i;
        if (q >= SS) continue;
        float inv = 1.f / l_r[i];
        float* op = g_O + ((size_t)b * SS + q) * DM + h * DH + tx * 4;
        op[0] = o[i][0] * inv; op[1] = o[i][1] * inv;
        op[2] = o[i][2] * inv; op[3] = o[i][3] * inv;
    }
}

// ---------------- residual add ----------------
__global__ void add_k()
{
    int idx = blockIdx.x * 256 + threadIdx.x;
    if (idx < BB * SS * DM) g_X[idx] += g_O[idx];
}

// ---------------- row L2 normalize over DM ----------------
__global__ void norm_k(float* __restrict__ buf)
{
    __shared__ float red[256];
    int tid = threadIdx.x;
    float* p = buf + (size_t)blockIdx.x * DM;
    float v0 = p[tid], v1 = p[tid + 256], v2 = p[tid + 512];
    float ss = blockReduceSum(v0*v0 + v1*v1 + v2*v2, red);
    float inv = 1.f / sqrtf(ss);
    p[tid] = v0 * inv; p[tid + 256] = v1 * inv; p[tid + 512] = v2 * inv;
}

// ---------------- masks: dot(patch, cls) + LN over 19 classes ----------------
__global__ void mask_k(const float* __restrict__ mg, const float* __restrict__ mb)
{
    __shared__ float sp[DM];
    __shared__ float red[128];
    __shared__ float arr[NCLS];
    __shared__ float stats[2];
    int b = blockIdx.y, n = blockIdx.x, tid = threadIdx.x;
    const float* pr = g_PA + ((size_t)b * NTOK + n) * DM;
    for (int i = tid; i < DM; i += 128) sp[i] = pr[i];
    __syncthreads();
    for (int c = 0; c < NCLS; c++) {
        const float* cr = g_CL + ((size_t)b * NCLS + c) * DM;
        float part = 0.f;
        for (int i = tid; i < DM; i += 128) part += sp[i] * cr[i];
        red[tid] = part; __syncthreads();
        for (int s = 64; s > 0; s >>= 1) {
            if (tid < s) red[tid] += red[tid + s];
            __syncthreads();
        }
        if (tid == 0) arr[c] = red[0];
        __syncthreads();
    }
    if (tid == 0) {
        float m = 0.f;
        for (int c = 0; c < NCLS; c++) m += arr[c];
        m *= (1.f / NCLS);
        float v = 0.f;
        for (int c = 0; c < NCLS; c++) { float d = arr[c] - m; v += d * d; }
        v *= (1.f / NCLS);
        stats[0] = m;
        stats[1] = rsqrtf(v + 1e-5f);
    }
    __syncthreads();
    if (tid < NCLS) {
        float val = (arr[tid] - stats[0]) * stats[1] * mg[tid] + mb[tid];
        g_MS[((size_t)b * NCLS + tid) * NTOK + n] = val;
    }
}

// ---------------- bilinear 32x32 -> 512x512 (half-pixel, edge clamp) ----------------
__global__ void resize_k(float* __restrict__ out)
{
    size_t idx = (size_t)blockIdx.x * 256 + threadIdx.x;
    if (idx >= (size_t)BB * NCLS * IMG * IMG) return;
    int x = (int)(idx & (IMG - 1));
    int y = (int)((idx >> 9) & (IMG - 1));
    int bc = (int)(idx >> 18);
    float fy = (y + 0.5f) * 0.0625f - 0.5f;
    float fx = (x + 0.5f) * 0.0625f - 0.5f;
    int y0 = (int)floorf(fy); float wy = fy - (float)y0;
    int x0 = (int)floorf(fx); float wx = fx - (float)x0;
    int y0c = max(y0, 0), y1c = min(y0 + 1, GSZ - 1);
    int x0c = max(x0, 0), x1c = min(x0 + 1, GSZ - 1);
    const float* mp = g_MS + (size_t)bc * NTOK;
    float v00 = mp[y0c * GSZ + x0c], v01 = mp[y0c * GSZ + x1c];
    float v10 = mp[y1c * GSZ + x0c], v11 = mp[y1c * GSZ + x1c];
    out[idx] = (1.f - wy) * ((1.f - wx) * v00 + wx * v01)
             +        wy  * ((1.f - wx) * v10 + wx * v11);
}

// ---------------- launch ----------------
extern "C" void kernel_launch(void* const* d_in, const int* in_sizes, int n_in,
                              void* d_out, int out_size)
{
    const float* x          = (const float*)d_in[0];
    const float* proj_dec_W = (const float*)d_in[1];
    const float* proj_dec_b = (const float*)d_in[2];
    const float* cls_emb    = (const float*)d_in[3];
    const float* ln1_g      = (const float*)d_in[4];
    const float* ln1_b      = (const float*)d_in[5];
    const float* qW         = (const float*)d_in[6];
    const float* qb         = (const float*)d_in[7];
    const float* kW         = (const float*)d_in[8];
    const float* kb         = (const float*)d_in[9];
    const float* vW         = (const float*)d_in[10];
    const float* vb         = (const float*)d_in[11];
    const float* ln2_g      = (const float*)d_in[12];
    const float* ln2_b      = (const float*)d_in[13];
    const float* mlp_W1     = (const float*)d_in[14];
    const float* mlp_b1     = (const float*)d_in[15];
    const float* mlp_W2     = (const float*)d_in[16];
    const float* mlp_b2     = (const float*)d_in[17];
    const float* proj_patch = (const float*)d_in[18];
    const float* proj_cls   = (const float*)d_in[19];
    const float* dec_g      = (const float*)d_in[20];
    const float* dec_b      = (const float*)d_in[21];
    const float* mask_g     = (const float*)d_in[22];
    const float* mask_b     = (const float*)d_in[23];

    float *X, *Hb, *FF, *PA, *CL;
    cudaGetSymbolAddress((void**)&X,  g_X);
    cudaGetSymbolAddress((void**)&Hb, g_Hb);
    cudaGetSymbolAddress((void**)&FF, g_FF);
    cudaGetSymbolAddress((void**)&PA, g_PA);
    cudaGetSymbolAddress((void**)&CL, g_CL);

    const int Mtok = BB * NTOK;  // 8192
    const int Mall = BB * SS;    // 8344

    // x @ proj_dec_W + b  ->  X (patch rows of ragged layout)
    sgemm_k<false><<<dim3(DM/128, Mtok/128), 256>>>(
        x, proj_dec_W, proj_dec_b, nullptr, X, Mtok, DM, DM, 0, 0, NTOK, SS);
    cls_copy_k<<<(BB*NCLS*DM + 255)/256, 256>>>(cls_emb);

    for (int l = 0; l < 2; l++) {
        ln_k<<<Mall, 256>>>(X, ln1_g + l*DM, ln1_b + l*DM, Hb);
        qkv_k<<<dim3((SS + 31)/32, NH, BB), 256>>>(qW, qb, kW, kb, vW, vb, l);
        flash_attn_k<<<dim3((SS + 63)/64, BB*NH), 256>>>();
        add_k<<<(BB*SS*DM + 255)/256, 256>>>();
        ln_k<<<Mall, 256>>>(X, ln2_g + l*DM, ln2_b + l*DM, Hb);
        sgemm_k<true><<<dim3(DFF/128, (Mall+127)/128), 256>>>(
            Hb, mlp_W1 + (size_t)l*DM*DFF, mlp_b1 + l*DFF, nullptr, FF,
            Mall, DFF, DM, 0, 0, 0, 0);
        sgemm_k<false><<<dim3(DM/128, (Mall+127)/128), 256>>>(
            FF, mlp_W2 + (size_t)l*DFF*DM, mlp_b2 + l*DM, X, X,
            Mall, DM, DFF, 0, 0, 0, 0);
    }

    ln_k<<<Mall, 256>>>(X, dec_g, dec_b, Hb);
    sgemm_k<false><<<dim3(DM/128, Mtok/128), 256>>>(
        Hb, proj_patch, nullptr, nullptr, PA, Mtok, DM, DM, NTOK, SS, 0, 0);
    sgemm_k<false><<<dim3(DM/128, (BB*NCLS + 127)/128), 256>>>(
        Hb + (size_t)NTOK*DM, proj_cls, nullptr, nullptr, CL, BB*NCLS, DM, DM, NCLS, SS, 0, 0);
    norm_k<<<Mtok, 256>>>(PA);
    norm_k<<<BB*NCLS, 256>>>(CL);
    mask_k<<<dim3(NTOK, BB), 128>>>(mask_g, mask_b);
    resize_k<<<(int)(((size_t)BB*NCLS*IMG*IMG + 255)/256), 256>>>((float*)d_out);
}

// round 5
// speedup vs baseline: 1.5500x; 1.5500x over previous
#include <cuda_runtime.h>
#include <cuda_bf16.h>
#include <cstdint>
#include <math.h>

#define BB   8
#define SS   1043
#define NTOK 1024
#define NCLS 19
#define DM   768
#define NH   12
#define DH   64
#define DFF  3072
#define GSZ  32
#define IMG  512

// ---------------- scratch (device globals; allocation-free) ----------------
__device__ float g_X [BB*SS*DM];
__device__ float g_Hb[BB*SS*DM];
__device__ float g_Q [BB*NH*SS*DH];
__device__ float g_K [BB*NH*SS*DH];
__device__ float g_V [BB*NH*SS*DH];
__device__ float g_O [BB*SS*DM];
__device__ float g_FF[BB*SS*DFF];
__device__ float g_PA[BB*NTOK*DM];
__device__ float g_CL[BB*NCLS*DM];
__device__ float g_MS[BB*NCLS*GSZ*GSZ];

// transposed + hi/lo-split weights (bf16), layout (N, K) row-major
#define OFF_PD 0
#define OFF_PP (768*768)
#define OFF_M1(l) (2*768*768 + (l)*768*3072)
#define OFF_M2(l) (2*768*768 + 2*768*3072 + (l)*768*3072)
#define WT_ELEMS (2*768*768 + 4*768*3072)
__device__ __nv_bfloat16 g_Wh[WT_ELEMS];
__device__ __nv_bfloat16 g_Wl[WT_ELEMS];

// ---------------- helpers ----------------
__device__ __forceinline__ float blockReduceSum(float v, float* red) {
    int tid = threadIdx.x;
    red[tid] = v; __syncthreads();
    for (int s = blockDim.x >> 1; s > 0; s >>= 1) {
        if (tid < s) red[tid] += red[tid + s];
        __syncthreads();
    }
    float r = red[0]; __syncthreads();
    return r;
}

__device__ __forceinline__ void mma16816(float* c, const uint32_t* a, const uint32_t* b) {
    asm volatile(
        "mma.sync.aligned.m16n8k16.row.col.f32.bf16.bf16.f32 "
        "{%0,%1,%2,%3}, {%4,%5,%6,%7}, {%8,%9}, {%0,%1,%2,%3};"
        : "+f"(c[0]), "+f"(c[1]), "+f"(c[2]), "+f"(c[3])
        : "r"(a[0]), "r"(a[1]), "r"(a[2]), "r"(a[3]), "r"(b[0]), "r"(b[1]));
}

// ---------------- weight transpose + split: W(K,N) -> Wt_hi/lo (N,K) bf16 ----------------
__global__ void wsplit_k(const float* __restrict__ W, __nv_bfloat16* __restrict__ Wh,
                         __nv_bfloat16* __restrict__ Wl, int K, int N)
{
    __shared__ float t[32][33];
    int bx = blockIdx.x * 32, by = blockIdx.y * 32;
    int tx = threadIdx.x, ty = threadIdx.y;
#pragma unroll
    for (int i = 0; i < 32; i += 8) {
        int k = by + ty + i, n = bx + tx;
        t[ty + i][tx] = (k < K && n < N) ? W[(size_t)k * N + n] : 0.f;
    }
    __syncthreads();
#pragma unroll
    for (int i = 0; i < 32; i += 8) {
        int n = bx + ty + i, k = by + tx;
        if (n < N && k < K) {
            float v = t[tx][ty + i];
            __nv_bfloat16 h = __float2bfloat16(v);
            Wh[(size_t)n * K + k] = h;
            Wl[(size_t)n * K + k] = __float2bfloat16(v - __bfloat162float(h));
        }
    }
}

// ---------------- HMMA GEMM: C = act(A@Wt^T + bias) [+ resid] ----------------
// A fp32 (M,K) row-major (opt ragged remap), Wt hi/lo bf16 (N,K) row-major.
// CTA tile 128x128, 8 warps (2m x 4n), warp tile 64x32, K-chunks of 32.
// Split-bf16 3-product: Ah*Bh + Ah*Bl + Al*Bh, fp32 accum.
#define P 40   // smem row pitch in bf16 elems
template<bool GELU>
__global__ void gemm_mma(const float* __restrict__ A,
                         const __nv_bfloat16* __restrict__ Bh, const __nv_bfloat16* __restrict__ Bl,
                         const float* __restrict__ bias, const float* __restrict__ resid,
                         float* __restrict__ C, int M, int N, int K,
                         int rpbA, int strA, int rpbC, int strC)
{
    __shared__ __nv_bfloat16 Ash[128][P], Asl[128][P], Bsh[128][P], Bsl[128][P];
    int tid = threadIdx.x;
    int wid = tid >> 5, lane = tid & 31;
    int wm = wid >> 2, wn = wid & 3;
    int g = lane >> 2, t2 = (lane & 3) * 2;
    int row0 = blockIdx.y * 128, col0 = blockIdx.x * 128;

    float acc[4][4][4];
#pragma unroll
    for (int mt = 0; mt < 4; mt++)
#pragma unroll
        for (int nt = 0; nt < 4; nt++)
#pragma unroll
            for (int i = 0; i < 4; i++) acc[mt][nt][i] = 0.f;

    const int NC = K / 32;
    for (int c = 0; c < NC; c++) {
        int k0 = c * 32;
        __syncthreads();
        // A: 128 rows x 32 k fp32 -> split bf16 hi/lo
#pragma unroll
        for (int j = 0; j < 4; j++) {
            int f = tid + j * 256;
            int row = f >> 3, k4 = f & 7;
            int gr = row0 + row;
            float4 v = make_float4(0.f, 0.f, 0.f, 0.f);
            if (gr < M) {
                size_t ar = rpbA ? (size_t)(gr / rpbA) * strA + (gr % rpbA) : (size_t)gr;
                v = *(const float4*)(A + ar * (size_t)K + k0 + k4 * 4);
            }
            __nv_bfloat162 h01 = __floats2bfloat162_rn(v.x, v.y);
            __nv_bfloat162 h23 = __floats2bfloat162_rn(v.z, v.w);
            __nv_bfloat162 l01 = __floats2bfloat162_rn(v.x - __bfloat162float(h01.x),
                                                       v.y - __bfloat162float(h01.y));
            __nv_bfloat162 l23 = __floats2bfloat162_rn(v.z - __bfloat162float(h23.x),
                                                       v.w - __bfloat162float(h23.y));
            *(__nv_bfloat162*)&Ash[row][k4*4]     = h01;
            *(__nv_bfloat162*)&Ash[row][k4*4 + 2] = h23;
            *(__nv_bfloat162*)&Asl[row][k4*4]     = l01;
            *(__nv_bfloat162*)&Asl[row][k4*4 + 2] = l23;
        }
        // B: 128 n-rows x 32 k bf16 hi/lo
#pragma unroll
        for (int j = 0; j < 2; j++) {
            int f = tid + j * 256;
            int row = f >> 2, k8 = f & 3;
            size_t src = (size_t)(col0 + row) * K + k0 + k8 * 8;
            *(float4*)&Bsh[row][k8*8] = *(const float4*)(Bh + src);
            *(float4*)&Bsl[row][k8*8] = *(const float4*)(Bl + src);
        }
        __syncthreads();

#pragma unroll
        for (int ks = 0; ks < 2; ks++) {
            int kb = ks * 16;
            uint32_t ah[4][4], al[4][4], bh[4][2], bl[4][2];
#pragma unroll
            for (int mt = 0; mt < 4; mt++) {
                int r0 = wm * 64 + mt * 16 + g;
                ah[mt][0] = *(uint32_t*)&Ash[r0][kb + t2];
                ah[mt][1] = *(uint32_t*)&Ash[r0 + 8][kb + t2];
                ah[mt][2] = *(uint32_t*)&Ash[r0][kb + t2 + 8];
                ah[mt][3] = *(uint32_t*)&Ash[r0 + 8][kb + t2 + 8];
                al[mt][0] = *(uint32_t*)&Asl[r0][kb + t2];
                al[mt][1] = *(uint32_t*)&Asl[r0 + 8][kb + t2];
                al[mt][2] = *(uint32_t*)&Asl[r0][kb + t2 + 8];
                al[mt][3] = *(uint32_t*)&Asl[r0 + 8][kb + t2 + 8];
            }
#pragma unroll
            for (int nt = 0; nt < 4; nt++) {
                int n0 = wn * 32 + nt * 8 + g;
                bh[nt][0] = *(uint32_t*)&Bsh[n0][kb + t2];
                bh[nt][1] = *(uint32_t*)&Bsh[n0][kb + t2 + 8];
                bl[nt][0] = *(uint32_t*)&Bsl[n0][kb + t2];
                bl[nt][1] = *(uint32_t*)&Bsl[n0][kb + t2 + 8];
            }
#pragma unroll
            for (int mt = 0; mt < 4; mt++)
#pragma unroll
                for (int nt = 0; nt < 4; nt++) {
                    mma16816(acc[mt][nt], ah[mt], bh[nt]);
                    mma16816(acc[mt][nt], ah[mt], bl[nt]);
                    mma16816(acc[mt][nt], al[mt], bh[nt]);
                }
        }
    }

    // epilogue
#pragma unroll
    for (int mt = 0; mt < 4; mt++) {
#pragma unroll
        for (int half = 0; half < 2; half++) {
            int gr = row0 + wm * 64 + mt * 16 + g + half * 8;
            if (gr >= M) continue;
            size_t cr = rpbC ? (size_t)(gr / rpbC) * strC + (gr % rpbC) : (size_t)gr;
#pragma unroll
            for (int nt = 0; nt < 4; nt++) {
                int gc = col0 + wn * 32 + nt * 8 + t2;
                float v0 = acc[mt][nt][half * 2];
                float v1 = acc[mt][nt][half * 2 + 1];
                if (bias) { v0 += __ldg(&bias[gc]); v1 += __ldg(&bias[gc + 1]); }
                if (GELU) {
                    v0 = 0.5f * v0 * (1.f + erff(v0 * 0.70710678118654752f));
                    v1 = 0.5f * v1 * (1.f + erff(v1 * 0.70710678118654752f));
                }
                size_t o = cr * (size_t)N + gc;
                if (resid) {
                    float2 rr = *(const float2*)(resid + o);
                    v0 += rr.x; v1 += rr.y;
                }
                *(float2*)(C + o) = make_float2(v0, v1);
            }
        }
    }
}

// ---------------- generic SIMT SGEMM (tiny proj_cls only) ----------------
template<bool GELU>
__global__ void sgemm_k(const float* __restrict__ A, const float* __restrict__ Bw,
                        const float* __restrict__ bias, const float* __restrict__ resid,
                        float* __restrict__ C, int M, int N, int K,
                        int rpbA, int strA, int rpbC, int strC)
{
    __shared__ float As[16][132];
    __shared__ float Bs[16][132];
    int tid = threadIdx.x;
    int row0 = blockIdx.y * 128, col0 = blockIdx.x * 128;
    int ty = tid >> 4, tx = tid & 15;
    float acc[8][8];
#pragma unroll
    for (int i = 0; i < 8; i++)
#pragma unroll
        for (int j = 0; j < 8; j++) acc[i][j] = 0.f;

    for (int k0 = 0; k0 < K; k0 += 16) {
#pragma unroll
        for (int i = 0; i < 2; i++) {
            int f = tid * 2 + i;
            int r = f >> 2, c4 = f & 3;
            int gr = row0 + r;
            float4 v = make_float4(0.f, 0.f, 0.f, 0.f);
            if (gr < M) {
                size_t ar = rpbA ? (size_t)(gr / rpbA) * strA + (gr % rpbA) : (size_t)gr;
                v = *(const float4*)(A + ar * (size_t)K + k0 + c4 * 4);
            }
            As[c4*4+0][r] = v.x; As[c4*4+1][r] = v.y;
            As[c4*4+2][r] = v.z; As[c4*4+3][r] = v.w;
        }
#pragma unroll
        for (int i = 0; i < 2; i++) {
            int f = tid * 2 + i;
            int r = f >> 5, c = (f & 31) * 4;
            float4 v = *(const float4*)(Bw + (size_t)(k0 + r) * N + col0 + c);
            *(float4*)&Bs[r][c] = v;
        }
        __syncthreads();
#pragma unroll
        for (int k = 0; k < 16; k++) {
            float a[8], b[8];
            *(float4*)(a)     = *(float4*)&As[k][ty*8];
            *(float4*)(a + 4) = *(float4*)&As[k][ty*8+4];
            *(float4*)(b)     = *(float4*)&Bs[k][tx*8];
            *(float4*)(b + 4) = *(float4*)&Bs[k][tx*8+4];
#pragma unroll
            for (int i = 0; i < 8; i++)
#pragma unroll
                for (int j = 0; j < 8; j++) acc[i][j] = fmaf(a[i], b[j], acc[i][j]);
        }
        __syncthreads();
    }
#pragma unroll
    for (int i = 0; i < 8; i++) {
        int gr = row0 + ty * 8 + i;
        if (gr >= M) continue;
        size_t cr = rpbC ? (size_t)(gr / rpbC) * strC + (gr % rpbC) : (size_t)gr;
#pragma unroll
        for (int j = 0; j < 8; j++) {
            int gc = col0 + tx * 8 + j;
            float v = acc[i][j];
            if (bias) v += __ldg(&bias[gc]);
            if (GELU) v = 0.5f * v * (1.f + erff(v * 0.70710678118654752f));
            if (resid) v += resid[cr * (size_t)N + gc];
            C[cr * (size_t)N + gc] = v;
        }
    }
}

// ---------------- cls token append ----------------
__global__ void cls_copy_k(const float* __restrict__ cls_emb)
{
    int idx = blockIdx.x * 256 + threadIdx.x;
    if (idx >= BB * NCLS * DM) return;
    int b = idx / (NCLS * DM);
    int rem = idx % (NCLS * DM);
    g_X[((size_t)b * SS + NTOK) * DM + rem] = cls_emb[rem];
}

// ---------------- LayerNorm over DM ----------------
__global__ void ln_k(const float* __restrict__ in, const float* __restrict__ g,
                     const float* __restrict__ be, float* __restrict__ out)
{
    __shared__ float red[256];
    int tid = threadIdx.x;
    const float* p = in + (size_t)blockIdx.x * DM;
    float v0 = p[tid], v1 = p[tid + 256], v2 = p[tid + 512];
    float m = blockReduceSum(v0 + v1 + v2, red) * (1.f / 768.f);
    float d0 = v0 - m, d1 = v1 - m, d2 = v2 - m;
    float var = blockReduceSum(d0*d0 + d1*d1 + d2*d2, red) * (1.f / 768.f);
    float inv = rsqrtf(var + 1e-5f);
    float* o = out + (size_t)blockIdx.x * DM;
    o[tid]       = d0 * inv * g[tid]       + be[tid];
    o[tid + 256] = d1 * inv * g[tid + 256] + be[tid + 256];
    o[tid + 512] = d2 * inv * g[tid + 512] + be[tid + 512];
}

// ---------------- per-head QKV projection ----------------
__global__ void qkv_k(const float* __restrict__ qW, const float* __restrict__ qb,
                      const float* __restrict__ kW, const float* __restrict__ kb,
                      const float* __restrict__ vW, const float* __restrict__ vb,
                      int l)
{
    __shared__ float sW[64][68];
    __shared__ float sH[64][65];
    int m = blockIdx.z % 3, b = blockIdx.z / 3;
    int h = blockIdx.y, s0 = blockIdx.x * 64;
    int tid = threadIdx.x;
    const float* W = (m == 0 ? qW : m == 1 ? kW : vW) + ((size_t)l * NH + h) * DH * DH;
    const float* bi = (m == 0 ? qb : m == 1 ? kb : vb) + ((size_t)l * NH + h) * DH;
    float* out = (m == 0 ? g_Q : m == 1 ? g_K : g_V) + ((size_t)b * NH + h) * SS * DH;

#pragma unroll
    for (int j = 0; j < 4; j++) {
        int f = tid + j * 256;
        int d = f >> 4, e4 = f & 15;
        *(float4*)&sW[d][e4 * 4] = *(const float4*)(W + d * DH + e4 * 4);
        int sl = f >> 4, d4 = f & 15;
        int s = s0 + sl;
        float4 v = make_float4(0.f, 0.f, 0.f, 0.f);
        if (s < SS) v = *(const float4*)(g_Hb + ((size_t)b * SS + s) * DM + h * DH + d4 * 4);
        sH[sl][d4*4+0] = v.x; sH[sl][d4*4+1] = v.y;
        sH[sl][d4*4+2] = v.z; sH[sl][d4*4+3] = v.w;
    }
    __syncthreads();

    int ty = tid >> 4, tx = tid & 15;
    float acc[4][4];
#pragma unroll
    for (int i = 0; i < 4; i++)
#pragma unroll
        for (int j = 0; j < 4; j++) acc[i][j] = 0.f;
#pragma unroll 8
    for (int k = 0; k < 64; k++) {
        float4 bv = *(float4*)&sW[k][tx * 4];
#pragma unroll
        for (int i = 0; i < 4; i++) {
            float a = sH[ty * 4 + i][k];
            acc[i][0] = fmaf(a, bv.x, acc[i][0]);
            acc[i][1] = fmaf(a, bv.y, acc[i][1]);
            acc[i][2] = fmaf(a, bv.z, acc[i][2]);
            acc[i][3] = fmaf(a, bv.w, acc[i][3]);
        }
    }
    float4 bb = *(const float4*)(bi + tx * 4);
#pragma unroll
    for (int i = 0; i < 4; i++) {
        int s = s0 + ty * 4 + i;
        if (s >= SS) continue;
        float4 v = make_float4(acc[i][0] + bb.x, acc[i][1] + bb.y,
                               acc[i][2] + bb.z, acc[i][3] + bb.w);
        *(float4*)(out + (size_t)s * DH + tx * 4) = v;
    }
}

// ---------------- fused flash attention ----------------
__global__ void flash_attn_k()
{
    __shared__ float Qs[64][68];
    __shared__ float Ks[32][65];
    __shared__ float Vs[32][68];
    __shared__ float Ps[64][36];

    int bh = blockIdx.y;
    int b = bh / NH, h = bh % NH;
    int q0 = blockIdx.x * 64;
    int tid = threadIdx.x;
    int ty = tid >> 4, tx = tid & 15;

    const float* Qb = g_Q + (size_t)bh * SS * DH;
    const float* Kb = g_K + (size_t)bh * SS * DH;
    const float* Vb = g_V + (size_t)bh * SS * DH;

#pragma unroll
    for (int i = 0; i < 4; i++) {
        int f = tid + i * 256;
        int r = f >> 4, c = (f & 15) * 4;
        float4 v = make_float4(0.f,0.f,0.f,0.f);
        if (q0 + r < SS) v = *(const float4*)(Qb + (size_t)(q0 + r) * DH + c);
        *(float4*)&Qs[r][c] = v;
    }

    float m_r[4], l_r[4], o[4][4];
#pragma unroll
    for (int i = 0; i < 4; i++) {
        m_r[i] = -3.4e38f; l_r[i] = 0.f;
#pragma unroll
        for (int j = 0; j < 4; j++) o[i][j] = 0.f;
    }

    const int NKT = (SS + 31) / 32;
    for (int kt = 0; kt < NKT; kt++) {
        int k0 = kt * 32;
        __syncthreads();
#pragma unroll
        for (int i = 0; i < 2; i++) {
            int f = tid + i * 256;
            int r = f >> 4, c = (f & 15) * 4;
            float4 kv = make_float4(0.f,0.f,0.f,0.f);
            float4 vv = make_float4(0.f,0.f,0.f,0.f);
            if (k0 + r < SS) {
                kv = *(const float4*)(Kb + (size_t)(k0 + r) * DH + c);
                vv = *(const float4*)(Vb + (size_t)(k0 + r) * DH + c);
            }
            Ks[r][c] = kv.x; Ks[r][c+1] = kv.y; Ks[r][c+2] = kv.z; Ks[r][c+3] = kv.w;
            *(float4*)&Vs[r][c] = vv;
        }
        __syncthreads();

        float s[4][2];
#pragma unroll
        for (int i = 0; i < 4; i++) { s[i][0] = 0.f; s[i][1] = 0.f; }
#pragma unroll 8
        for (int k = 0; k < 64; k++) {
            float b0 = Ks[tx*2][k], b1 = Ks[tx*2+1][k];
#pragma unroll
            for (int i = 0; i < 4; i++) {
                float a = Qs[ty*4+i][k];
                s[i][0] = fmaf(a, b0, s[i][0]);
                s[i][1] = fmaf(a, b1, s[i][1]);
            }
        }
        bool ok0 = (k0 + tx*2)     < SS;
        bool ok1 = (k0 + tx*2 + 1) < SS;
#pragma unroll
        for (int i = 0; i < 4; i++) {
            s[i][0] = ok0 ? s[i][0] * 0.125f : -3.4e38f;
            s[i][1] = ok1 ? s[i][1] * 0.125f : -3.4e38f;
        }

        float p[4][2];
#pragma unroll
        for (int i = 0; i < 4; i++) {
            float mx = fmaxf(s[i][0], s[i][1]);
#pragma unroll
            for (int off = 8; off > 0; off >>= 1)
                mx = fmaxf(mx, __shfl_xor_sync(0xffffffffu, mx, off, 16));
            float newm = fmaxf(m_r[i], mx);
            float corr = __expf(m_r[i] - newm);
            p[i][0] = __expf(s[i][0] - newm);
            p[i][1] = __expf(s[i][1] - newm);
            float rs = p[i][0] + p[i][1];
#pragma unroll
            for (int off = 8; off > 0; off >>= 1)
                rs += __shfl_xor_sync(0xffffffffu, rs, off, 16);
            l_r[i] = l_r[i] * corr + rs;
            m_r[i] = newm;
#pragma unroll
            for (int j = 0; j < 4; j++) o[i][j] *= corr;
        }
#pragma unroll
        for (int i = 0; i < 4; i++) {
            Ps[ty*4+i][tx*2]   = p[i][0];
            Ps[ty*4+i][tx*2+1] = p[i][1];
        }
        __syncthreads();

#pragma unroll 4
        for (int k = 0; k < 32; k++) {
            float4 vv = *(float4*)&Vs[k][tx*4];
#pragma unroll
            for (int i = 0; i < 4; i++) {
                float pv = Ps[ty*4+i][k];
                o[i][0] = fmaf(pv, vv.x, o[i][0]);
                o[i][1] = fmaf(pv, vv.y, o[i][1]);
                o[i][2] = fmaf(pv, vv.z, o[i][2]);
                o[i][3] = fmaf(pv, vv.w, o[i][3]);
            }
        }
    }

#pragma unroll
    for (int i = 0; i < 4; i++) {
        int q = q0 + ty*4 + i;
        if (q >= SS) continue;
        float inv = 1.f / l_r[i];
        float* op = g_O + ((size_t)b * SS + q) * DM + h * DH + tx * 4;
        op[0] = o[i][0] * inv; op[1] = o[i][1] * inv;
        op[2] = o[i][2] * inv; op[3] = o[i][3] * inv;
    }
}

// ---------------- residual add ----------------
__global__ void add_k()
{
    int idx = blockIdx.x * 256 + threadIdx.x;
    if (idx < BB * SS * DM) g_X[idx] += g_O[idx];
}

// ---------------- row L2 normalize over DM ----------------
__global__ void norm_k(float* __restrict__ buf)
{
    __shared__ float red[256];
    int tid = threadIdx.x;
    float* p = buf + (size_t)blockIdx.x * DM;
    float v0 = p[tid], v1 = p[tid + 256], v2 = p[tid + 512];
    float ss = blockReduceSum(v0*v0 + v1*v1 + v2*v2, red);
    float inv = 1.f / sqrtf(ss);
    p[tid] = v0 * inv; p[tid + 256] = v1 * inv; p[tid + 512] = v2 * inv;
}

// ---------------- masks: dot(patch, cls) + LN over 19 classes ----------------
__global__ void mask_k(const float* __restrict__ mg, const float* __restrict__ mb)
{
    __shared__ float sp[DM];
    __shared__ float red[128];
    __shared__ float arr[NCLS];
    __shared__ float stats[2];
    int b = blockIdx.y, n = blockIdx.x, tid = threadIdx.x;
    const float* pr = g_PA + ((size_t)b * NTOK + n) * DM;
    for (int i = tid; i < DM; i += 128) sp[i] = pr[i];
    __syncthreads();
    for (int c = 0; c < NCLS; c++) {
        const float* cr = g_CL + ((size_t)b * NCLS + c) * DM;
        float part = 0.f;
        for (int i = tid; i < DM; i += 128) part += sp[i] * cr[i];
        red[tid] = part; __syncthreads();
        for (int s = 64; s > 0; s >>= 1) {
            if (tid < s) red[tid] += red[tid + s];
            __syncthreads();
        }
        if (tid == 0) arr[c] = red[0];
        __syncthreads();
    }
    if (tid == 0) {
        float m = 0.f;
        for (int c = 0; c < NCLS; c++) m += arr[c];
        m *= (1.f / NCLS);
        float v = 0.f;
        for (int c = 0; c < NCLS; c++) { float d = arr[c] - m; v += d * d; }
        v *= (1.f / NCLS);
        stats[0] = m;
        stats[1] = rsqrtf(v + 1e-5f);
    }
    __syncthreads();
    if (tid < NCLS) {
        float val = (arr[tid] - stats[0]) * stats[1] * mg[tid] + mb[tid];
        g_MS[((size_t)b * NCLS + tid) * NTOK + n] = val;
    }
}

// ---------------- bilinear 32x32 -> 512x512 ----------------
__global__ void resize_k(float* __restrict__ out)
{
    size_t idx = (size_t)blockIdx.x * 256 + threadIdx.x;
    if (idx >= (size_t)BB * NCLS * IMG * IMG) return;
    int x = (int)(idx & (IMG - 1));
    int y = (int)((idx >> 9) & (IMG - 1));
    int bc = (int)(idx >> 18);
    float fy = (y + 0.5f) * 0.0625f - 0.5f;
    float fx = (x + 0.5f) * 0.0625f - 0.5f;
    int y0 = (int)floorf(fy); float wy = fy - (float)y0;
    int x0 = (int)floorf(fx); float wx = fx - (float)x0;
    int y0c = max(y0, 0), y1c = min(y0 + 1, GSZ - 1);
    int x0c = max(x0, 0), x1c = min(x0 + 1, GSZ - 1);
    const float* mp = g_MS + (size_t)bc * NTOK;
    float v00 = mp[y0c * GSZ + x0c], v01 = mp[y0c * GSZ + x1c];
    float v10 = mp[y1c * GSZ + x0c], v11 = mp[y1c * GSZ + x1c];
    out[idx] = (1.f - wy) * ((1.f - wx) * v00 + wx * v01)
             +        wy  * ((1.f - wx) * v10 + wx * v11);
}

// ---------------- launch ----------------
extern "C" void kernel_launch(void* const* d_in, const int* in_sizes, int n_in,
                              void* d_out, int out_size)
{
    const float* x          = (const float*)d_in[0];
    const float* proj_dec_W = (const float*)d_in[1];
    const float* proj_dec_b = (const float*)d_in[2];
    const float* cls_emb    = (const float*)d_in[3];
    const float* ln1_g      = (const float*)d_in[4];
    const float* ln1_b      = (const float*)d_in[5];
    const float* qW         = (const float*)d_in[6];
    const float* qb         = (const float*)d_in[7];
    const float* kW         = (const float*)d_in[8];
    const float* kb         = (const float*)d_in[9];
    const float* vW         = (const float*)d_in[10];
    const float* vb         = (const float*)d_in[11];
    const float* ln2_g      = (const float*)d_in[12];
    const float* ln2_b      = (const float*)d_in[13];
    const float* mlp_W1     = (const float*)d_in[14];
    const float* mlp_b1     = (const float*)d_in[15];
    const float* mlp_W2     = (const float*)d_in[16];
    const float* mlp_b2     = (const float*)d_in[17];
    const float* proj_patch = (const float*)d_in[18];
    const float* proj_cls   = (const float*)d_in[19];
    const float* dec_g      = (const float*)d_in[20];
    const float* dec_b      = (const float*)d_in[21];
    const float* mask_g     = (const float*)d_in[22];
    const float* mask_b     = (const float*)d_in[23];

    float *X, *Hb, *FF, *PA, *CL;
    __nv_bfloat16 *Wh, *Wl;
    cudaGetSymbolAddress((void**)&X,  g_X);
    cudaGetSymbolAddress((void**)&Hb, g_Hb);
    cudaGetSymbolAddress((void**)&FF, g_FF);
    cudaGetSymbolAddress((void**)&PA, g_PA);
    cudaGetSymbolAddress((void**)&CL, g_CL);
    cudaGetSymbolAddress((void**)&Wh, g_Wh);
    cudaGetSymbolAddress((void**)&Wl, g_Wl);

    const int Mtok = BB * NTOK;  // 8192
    const int Mall = BB * SS;    // 8344
    dim3 wb(32, 8);

    // weight transpose + split (cheap, every launch)
    wsplit_k<<<dim3(24, 24), wb>>>(proj_dec_W, Wh + OFF_PD, Wl + OFF_PD, 768, 768);
    wsplit_k<<<dim3(24, 24), wb>>>(proj_patch, Wh + OFF_PP, Wl + OFF_PP, 768, 768);
    for (int l = 0; l < 2; l++) {
        wsplit_k<<<dim3(96, 24), wb>>>(mlp_W1 + (size_t)l*DM*DFF, Wh + OFF_M1(l), Wl + OFF_M1(l), 768, 3072);
        wsplit_k<<<dim3(24, 96), wb>>>(mlp_W2 + (size_t)l*DFF*DM, Wh + OFF_M2(l), Wl + OFF_M2(l), 3072, 768);
    }

    // x @ proj_dec_W + b -> X (ragged rows)
    gemm_mma<false><<<dim3(6, 64), 256>>>(
        x, Wh + OFF_PD, Wl + OFF_PD, proj_dec_b, nullptr, X, Mtok, DM, DM, 0, 0, NTOK, SS);
    cls_copy_k<<<(BB*NCLS*DM + 255)/256, 256>>>(cls_emb);

    for (int l = 0; l < 2; l++) {
        ln_k<<<Mall, 256>>>(X, ln1_g + l*DM, ln1_b + l*DM, Hb);
        qkv_k<<<dim3((SS + 63)/64, NH, BB*3), 256>>>(qW, qb, kW, kb, vW, vb, l);
        flash_attn_k<<<dim3((SS + 63)/64, BB*NH), 256>>>();
        add_k<<<(BB*SS*DM + 255)/256, 256>>>();
        ln_k<<<Mall, 256>>>(X, ln2_g + l*DM, ln2_b + l*DM, Hb);
        gemm_mma<true><<<dim3(24, 66), 256>>>(
            Hb, Wh + OFF_M1(l), Wl + OFF_M1(l), mlp_b1 + l*DFF, nullptr, FF,
            Mall, DFF, DM, 0, 0, 0, 0);
        gemm_mma<false><<<dim3(6, 66), 256>>>(
            FF, Wh + OFF_M2(l), Wl + OFF_M2(l), mlp_b2 + l*DM, X, X,
            Mall, DM, DFF, 0, 0, 0, 0);
    }

    ln_k<<<Mall, 256>>>(X, dec_g, dec_b, Hb);
    gemm_mma<false><<<dim3(6, 64), 256>>>(
        Hb, Wh + OFF_PP, Wl + OFF_PP, nullptr, nullptr, PA, Mtok, DM, DM, NTOK, SS, 0, 0);
    sgemm_k<false><<<dim3(DM/128, (BB*NCLS + 127)/128), 256>>>(
        Hb + (size_t)NTOK*DM, proj_cls, nullptr, nullptr, CL, BB*NCLS, DM, DM, NCLS, SS, 0, 0);
    norm_k<<<Mtok, 256>>>(PA);
    norm_k<<<BB*NCLS, 256>>>(CL);
    mask_k<<<dim3(NTOK, BB), 128>>>(mask_g, mask_b);
    resize_k<<<(int)(((size_t)BB*NCLS*IMG*IMG + 255)/256), 256>>>((float*)d_out);
}

// round 6
// speedup vs baseline: 1.8237x; 1.1766x over previous
#include <cuda_runtime.h>
#include <cuda_bf16.h>
#include <cstdint>
#include <math.h>

#define BB   8
#define SS   1043
#define NTOK 1024
#define NCLS 19
#define DM   768
#define NH   12
#define DH   64
#define DFF  3072
#define GSZ  32
#define IMG  512

// ---------------- scratch (device globals; allocation-free) ----------------
__device__ float g_X [BB*SS*DM];
__device__ float g_Hb[BB*SS*DM];
__device__ float g_Q [BB*NH*SS*DH];
__device__ float g_K [BB*NH*SS*DH];
__device__ float g_V [BB*NH*SS*DH];
__device__ float g_FF[BB*SS*DFF];
__device__ float g_PA[BB*NTOK*DM];
__device__ float g_CL[BB*NCLS*DM];
__device__ float g_MS[BB*NCLS*GSZ*GSZ];

// transposed + hi/lo-split weights (bf16), layout (N, K) row-major
#define OFF_PD 0
#define OFF_PP (768*768)
#define OFF_M1(l) (2*768*768 + (l)*768*3072)
#define OFF_M2(l) (2*768*768 + 2*768*3072 + (l)*768*3072)
#define WT_ELEMS (2*768*768 + 4*768*3072)
__device__ __nv_bfloat16 g_Wh[WT_ELEMS];
__device__ __nv_bfloat16 g_Wl[WT_ELEMS];

// ---------------- helpers ----------------
__device__ __forceinline__ float blockReduceSum(float v, float* red) {
    int tid = threadIdx.x;
    red[tid] = v; __syncthreads();
    for (int s = blockDim.x >> 1; s > 0; s >>= 1) {
        if (tid < s) red[tid] += red[tid + s];
        __syncthreads();
    }
    float r = red[0]; __syncthreads();
    return r;
}

__device__ __forceinline__ void mma16816(float* c, const uint32_t* a, const uint32_t* b) {
    asm volatile(
        "mma.sync.aligned.m16n8k16.row.col.f32.bf16.bf16.f32 "
        "{%0,%1,%2,%3}, {%4,%5,%6,%7}, {%8,%9}, {%0,%1,%2,%3};"
        : "+f"(c[0]), "+f"(c[1]), "+f"(c[2]), "+f"(c[3])
        : "r"(a[0]), "r"(a[1]), "r"(a[2]), "r"(a[3]), "r"(b[0]), "r"(b[1]));
}
__device__ __forceinline__ uint32_t pack_bf16(float x, float y) {
    __nv_bfloat162 v = __floats2bfloat162_rn(x, y);
    return *(uint32_t*)&v;
}

// ---------------- weight transpose + split: W(K,N) -> Wt_hi/lo (N,K) bf16 ----------------
__global__ void wsplit_k(const float* __restrict__ W, __nv_bfloat16* __restrict__ Wh,
                         __nv_bfloat16* __restrict__ Wl, int K, int N)
{
    __shared__ float t[32][33];
    int bx = blockIdx.x * 32, by = blockIdx.y * 32;
    int tx = threadIdx.x, ty = threadIdx.y;
#pragma unroll
    for (int i = 0; i < 32; i += 8) {
        int k = by + ty + i, n = bx + tx;
        t[ty + i][tx] = (k < K && n < N) ? W[(size_t)k * N + n] : 0.f;
    }
    __syncthreads();
#pragma unroll
    for (int i = 0; i < 32; i += 8) {
        int n = bx + ty + i, k = by + tx;
        if (n < N && k < K) {
            float v = t[tx][ty + i];
            __nv_bfloat16 h = __float2bfloat16(v);
            Wh[(size_t)n * K + k] = h;
            Wl[(size_t)n * K + k] = __float2bfloat16(v - __bfloat162float(h));
        }
    }
}

// ---------------- HMMA GEMM: C = act(A@Wt^T + bias) [+ resid] ----------------
#define P 40   // smem row pitch in bf16 elems
template<bool GELU>
__global__ void gemm_mma(const float* __restrict__ A,
                         const __nv_bfloat16* __restrict__ Bh, const __nv_bfloat16* __restrict__ Bl,
                         const float* __restrict__ bias, const float* __restrict__ resid,
                         float* __restrict__ C, int M, int N, int K,
                         int rpbA, int strA, int rpbC, int strC)
{
    __shared__ __nv_bfloat16 Ash[128][P], Asl[128][P], Bsh[128][P], Bsl[128][P];
    int tid = threadIdx.x;
    int wid = tid >> 5, lane = tid & 31;
    int wm = wid >> 2, wn = wid & 3;
    int g = lane >> 2, t2 = (lane & 3) * 2;
    int row0 = blockIdx.y * 128, col0 = blockIdx.x * 128;

    float acc[4][4][4];
#pragma unroll
    for (int mt = 0; mt < 4; mt++)
#pragma unroll
        for (int nt = 0; nt < 4; nt++)
#pragma unroll
            for (int i = 0; i < 4; i++) acc[mt][nt][i] = 0.f;

    const int NC = K / 32;
    for (int c = 0; c < NC; c++) {
        int k0 = c * 32;
        __syncthreads();
#pragma unroll
        for (int j = 0; j < 4; j++) {
            int f = tid + j * 256;
            int row = f >> 3, k4 = f & 7;
            int gr = row0 + row;
            float4 v = make_float4(0.f, 0.f, 0.f, 0.f);
            if (gr < M) {
                size_t ar = rpbA ? (size_t)(gr / rpbA) * strA + (gr % rpbA) : (size_t)gr;
                v = *(const float4*)(A + ar * (size_t)K + k0 + k4 * 4);
            }
            __nv_bfloat162 h01 = __floats2bfloat162_rn(v.x, v.y);
            __nv_bfloat162 h23 = __floats2bfloat162_rn(v.z, v.w);
            __nv_bfloat162 l01 = __floats2bfloat162_rn(v.x - __bfloat162float(h01.x),
                                                       v.y - __bfloat162float(h01.y));
            __nv_bfloat162 l23 = __floats2bfloat162_rn(v.z - __bfloat162float(h23.x),
                                                       v.w - __bfloat162float(h23.y));
            *(__nv_bfloat162*)&Ash[row][k4*4]     = h01;
            *(__nv_bfloat162*)&Ash[row][k4*4 + 2] = h23;
            *(__nv_bfloat162*)&Asl[row][k4*4]     = l01;
            *(__nv_bfloat162*)&Asl[row][k4*4 + 2] = l23;
        }
#pragma unroll
        for (int j = 0; j < 2; j++) {
            int f = tid + j * 256;
            int row = f >> 2, k8 = f & 3;
            size_t src = (size_t)(col0 + row) * K + k0 + k8 * 8;
            *(float4*)&Bsh[row][k8*8] = *(const float4*)(Bh + src);
            *(float4*)&Bsl[row][k8*8] = *(const float4*)(Bl + src);
        }
        __syncthreads();

#pragma unroll
        for (int ks = 0; ks < 2; ks++) {
            int kb = ks * 16;
            uint32_t ah[4][4], al[4][4], bh[4][2], bl[4][2];
#pragma unroll
            for (int mt = 0; mt < 4; mt++) {
                int r0 = wm * 64 + mt * 16 + g;
                ah[mt][0] = *(uint32_t*)&Ash[r0][kb + t2];
                ah[mt][1] = *(uint32_t*)&Ash[r0 + 8][kb + t2];
                ah[mt][2] = *(uint32_t*)&Ash[r0][kb + t2 + 8];
                ah[mt][3] = *(uint32_t*)&Ash[r0 + 8][kb + t2 + 8];
                al[mt][0] = *(uint32_t*)&Asl[r0][kb + t2];
                al[mt][1] = *(uint32_t*)&Asl[r0 + 8][kb + t2];
                al[mt][2] = *(uint32_t*)&Asl[r0][kb + t2 + 8];
                al[mt][3] = *(uint32_t*)&Asl[r0 + 8][kb + t2 + 8];
            }
#pragma unroll
            for (int nt = 0; nt < 4; nt++) {
                int n0 = wn * 32 + nt * 8 + g;
                bh[nt][0] = *(uint32_t*)&Bsh[n0][kb + t2];
                bh[nt][1] = *(uint32_t*)&Bsh[n0][kb + t2 + 8];
                bl[nt][0] = *(uint32_t*)&Bsl[n0][kb + t2];
                bl[nt][1] = *(uint32_t*)&Bsl[n0][kb + t2 + 8];
            }
#pragma unroll
            for (int mt = 0; mt < 4; mt++)
#pragma unroll
                for (int nt = 0; nt < 4; nt++) {
                    mma16816(acc[mt][nt], ah[mt], bh[nt]);
                    mma16816(acc[mt][nt], ah[mt], bl[nt]);
                    mma16816(acc[mt][nt], al[mt], bh[nt]);
                }
        }
    }

#pragma unroll
    for (int mt = 0; mt < 4; mt++) {
#pragma unroll
        for (int half = 0; half < 2; half++) {
            int gr = row0 + wm * 64 + mt * 16 + g + half * 8;
            if (gr >= M) continue;
            size_t cr = rpbC ? (size_t)(gr / rpbC) * strC + (gr % rpbC) : (size_t)gr;
#pragma unroll
            for (int nt = 0; nt < 4; nt++) {
                int gc = col0 + wn * 32 + nt * 8 + t2;
                float v0 = acc[mt][nt][half * 2];
                float v1 = acc[mt][nt][half * 2 + 1];
                if (bias) { v0 += __ldg(&bias[gc]); v1 += __ldg(&bias[gc + 1]); }
                if (GELU) {
                    v0 = 0.5f * v0 * (1.f + erff(v0 * 0.70710678118654752f));
                    v1 = 0.5f * v1 * (1.f + erff(v1 * 0.70710678118654752f));
                }
                size_t o = cr * (size_t)N + gc;
                if (resid) {
                    float2 rr = *(const float2*)(resid + o);
                    v0 += rr.x; v1 += rr.y;
                }
                *(float2*)(C + o) = make_float2(v0, v1);
            }
        }
    }
}

// ---------------- generic SIMT SGEMM (tiny proj_cls only) ----------------
template<bool GELU>
__global__ void sgemm_k(const float* __restrict__ A, const float* __restrict__ Bw,
                        const float* __restrict__ bias, const float* __restrict__ resid,
                        float* __restrict__ C, int M, int N, int K,
                        int rpbA, int strA, int rpbC, int strC)
{
    __shared__ float As[16][132];
    __shared__ float Bs[16][132];
    int tid = threadIdx.x;
    int row0 = blockIdx.y * 128, col0 = blockIdx.x * 128;
    int ty = tid >> 4, tx = tid & 15;
    float acc[8][8];
#pragma unroll
    for (int i = 0; i < 8; i++)
#pragma unroll
        for (int j = 0; j < 8; j++) acc[i][j] = 0.f;

    for (int k0 = 0; k0 < K; k0 += 16) {
#pragma unroll
        for (int i = 0; i < 2; i++) {
            int f = tid * 2 + i;
            int r = f >> 2, c4 = f & 3;
            int gr = row0 + r;
            float4 v = make_float4(0.f, 0.f, 0.f, 0.f);
            if (gr < M) {
                size_t ar = rpbA ? (size_t)(gr / rpbA) * strA + (gr % rpbA) : (size_t)gr;
                v = *(const float4*)(A + ar * (size_t)K + k0 + c4 * 4);
            }
            As[c4*4+0][r] = v.x; As[c4*4+1][r] = v.y;
            As[c4*4+2][r] = v.z; As[c4*4+3][r] = v.w;
        }
#pragma unroll
        for (int i = 0; i < 2; i++) {
            int f = tid * 2 + i;
            int r = f >> 5, c = (f & 31) * 4;
            float4 v = *(const float4*)(Bw + (size_t)(k0 + r) * N + col0 + c);
            *(float4*)&Bs[r][c] = v;
        }
        __syncthreads();
#pragma unroll
        for (int k = 0; k < 16; k++) {
            float a[8], b[8];
            *(float4*)(a)     = *(float4*)&As[k][ty*8];
            *(float4*)(a + 4) = *(float4*)&As[k][ty*8+4];
            *(float4*)(b)     = *(float4*)&Bs[k][tx*8];
            *(float4*)(b + 4) = *(float4*)&Bs[k][tx*8+4];
#pragma unroll
            for (int i = 0; i < 8; i++)
#pragma unroll
                for (int j = 0; j < 8; j++) acc[i][j] = fmaf(a[i], b[j], acc[i][j]);
        }
        __syncthreads();
    }
#pragma unroll
    for (int i = 0; i < 8; i++) {
        int gr = row0 + ty * 8 + i;
        if (gr >= M) continue;
        size_t cr = rpbC ? (size_t)(gr / rpbC) * strC + (gr % rpbC) : (size_t)gr;
#pragma unroll
        for (int j = 0; j < 8; j++) {
            int gc = col0 + tx * 8 + j;
            float v = acc[i][j];
            if (bias) v += __ldg(&bias[gc]);
            if (GELU) v = 0.5f * v * (1.f + erff(v * 0.70710678118654752f));
            if (resid) v += resid[cr * (size_t)N + gc];
            C[cr * (size_t)N + gc] = v;
        }
    }
}

// ---------------- cls token append ----------------
__global__ void cls_copy_k(const float* __restrict__ cls_emb)
{
    int idx = blockIdx.x * 256 + threadIdx.x;
    if (idx >= BB * NCLS * DM) return;
    int b = idx / (NCLS * DM);
    int rem = idx % (NCLS * DM);
    g_X[((size_t)b * SS + NTOK) * DM + rem] = cls_emb[rem];
}

// ---------------- LayerNorm over DM ----------------
__global__ void ln_k(const float* __restrict__ in, const float* __restrict__ g,
                     const float* __restrict__ be, float* __restrict__ out)
{
    __shared__ float red[256];
    int tid = threadIdx.x;
    const float* p = in + (size_t)blockIdx.x * DM;
    float v0 = p[tid], v1 = p[tid + 256], v2 = p[tid + 512];
    float m = blockReduceSum(v0 + v1 + v2, red) * (1.f / 768.f);
    float d0 = v0 - m, d1 = v1 - m, d2 = v2 - m;
    float var = blockReduceSum(d0*d0 + d1*d1 + d2*d2, red) * (1.f / 768.f);
    float inv = rsqrtf(var + 1e-5f);
    float* o = out + (size_t)blockIdx.x * DM;
    o[tid]       = d0 * inv * g[tid]       + be[tid];
    o[tid + 256] = d1 * inv * g[tid + 256] + be[tid + 256];
    o[tid + 512] = d2 * inv * g[tid + 512] + be[tid + 512];
}

// ---------------- per-head QKV projection ----------------
__global__ void qkv_k(const float* __restrict__ qW, const float* __restrict__ qb,
                      const float* __restrict__ kW, const float* __restrict__ kb,
                      const float* __restrict__ vW, const float* __restrict__ vb,
                      int l)
{
    __shared__ float sW[64][68];
    __shared__ float sH[64][65];
    int m = blockIdx.z % 3, b = blockIdx.z / 3;
    int h = blockIdx.y, s0 = blockIdx.x * 64;
    int tid = threadIdx.x;
    const float* W = (m == 0 ? qW : m == 1 ? kW : vW) + ((size_t)l * NH + h) * DH * DH;
    const float* bi = (m == 0 ? qb : m == 1 ? kb : vb) + ((size_t)l * NH + h) * DH;
    float* out = (m == 0 ? g_Q : m == 1 ? g_K : g_V) + ((size_t)b * NH + h) * SS * DH;

#pragma unroll
    for (int j = 0; j < 4; j++) {
        int f = tid + j * 256;
        int d = f >> 4, e4 = f & 15;
        *(float4*)&sW[d][e4 * 4] = *(const float4*)(W + d * DH + e4 * 4);
        int sl = f >> 4, d4 = f & 15;
        int s = s0 + sl;
        float4 v = make_float4(0.f, 0.f, 0.f, 0.f);
        if (s < SS) v = *(const float4*)(g_Hb + ((size_t)b * SS + s) * DM + h * DH + d4 * 4);
        sH[sl][d4*4+0] = v.x; sH[sl][d4*4+1] = v.y;
        sH[sl][d4*4+2] = v.z; sH[sl][d4*4+3] = v.w;
    }
    __syncthreads();

    int ty = tid >> 4, tx = tid & 15;
    float acc[4][4];
#pragma unroll
    for (int i = 0; i < 4; i++)
#pragma unroll
        for (int j = 0; j < 4; j++) acc[i][j] = 0.f;
#pragma unroll 8
    for (int k = 0; k < 64; k++) {
        float4 bv = *(float4*)&sW[k][tx * 4];
#pragma unroll
        for (int i = 0; i < 4; i++) {
            float a = sH[ty * 4 + i][k];
            acc[i][0] = fmaf(a, bv.x, acc[i][0]);
            acc[i][1] = fmaf(a, bv.y, acc[i][1]);
            acc[i][2] = fmaf(a, bv.z, acc[i][2]);
            acc[i][3] = fmaf(a, bv.w, acc[i][3]);
        }
    }
    float4 bb = *(const float4*)(bi + tx * 4);
#pragma unroll
    for (int i = 0; i < 4; i++) {
        int s = s0 + ty * 4 + i;
        if (s >= SS) continue;
        float4 v = make_float4(acc[i][0] + bb.x, acc[i][1] + bb.y,
                               acc[i][2] + bb.z, acc[i][3] + bb.w);
        *(float4*)(out + (size_t)s * DH + tx * 4) = v;
    }
}

// ---------------- HMMA flash attention, fused X += O ----------------
// block: 128 threads (4 warps). Each block: 64 q rows of one (b,h).
// K-tiles of 64 keys. QK^T and PV via mma.sync split-bf16 (3 products).
#define FP 72   // smem pitch (bf16 elems)
__global__ void flash_mma_k()
{
    __shared__ __nv_bfloat16 sKh[64][FP], sKl[64][FP], sVh[64][FP], sVl[64][FP];

    int bh = blockIdx.y;
    int b = bh / NH, h = bh % NH;
    int q0 = blockIdx.x * 64;
    int tid = threadIdx.x;
    int wid = tid >> 5, lane = tid & 31;
    int g = lane >> 2, t2 = (lane & 3) * 2;
    int rw = wid * 16;   // warp's q-row base within tile

    const float* Qb = g_Q + (size_t)bh * SS * DH;
    const float* Kb = g_K + (size_t)bh * SS * DH;
    const float* Vb = g_V + (size_t)bh * SS * DH;

    // ---- stage Q (64x64 fp32 -> split bf16) into sKh/sKl, load frags ----
#pragma unroll
    for (int j = 0; j < 8; j++) {
        int f = tid + j * 128;
        int row = f >> 4, c4 = f & 15;
        float4 v = make_float4(0.f, 0.f, 0.f, 0.f);
        if (q0 + row < SS) v = *(const float4*)(Qb + (size_t)(q0 + row) * DH + c4 * 4);
        __nv_bfloat162 h01 = __floats2bfloat162_rn(v.x, v.y);
        __nv_bfloat162 h23 = __floats2bfloat162_rn(v.z, v.w);
        __nv_bfloat162 l01 = __floats2bfloat162_rn(v.x - __bfloat162float(h01.x),
                                                   v.y - __bfloat162float(h01.y));
        __nv_bfloat162 l23 = __floats2bfloat162_rn(v.z - __bfloat162float(h23.x),
                                                   v.w - __bfloat162float(h23.y));
        *(__nv_bfloat162*)&sKh[row][c4*4]     = h01;
        *(__nv_bfloat162*)&sKh[row][c4*4 + 2] = h23;
        *(__nv_bfloat162*)&sKl[row][c4*4]     = l01;
        *(__nv_bfloat162*)&sKl[row][c4*4 + 2] = l23;
    }
    __syncthreads();
    uint32_t qh[4][4], ql[4][4];
#pragma unroll
    for (int kc = 0; kc < 4; kc++) {
        int kb2 = kc * 16;
        qh[kc][0] = *(uint32_t*)&sKh[rw + g][kb2 + t2];
        qh[kc][1] = *(uint32_t*)&sKh[rw + g + 8][kb2 + t2];
        qh[kc][2] = *(uint32_t*)&sKh[rw + g][kb2 + t2 + 8];
        qh[kc][3] = *(uint32_t*)&sKh[rw + g + 8][kb2 + t2 + 8];
        ql[kc][0] = *(uint32_t*)&sKl[rw + g][kb2 + t2];
        ql[kc][1] = *(uint32_t*)&sKl[rw + g + 8][kb2 + t2];
        ql[kc][2] = *(uint32_t*)&sKl[rw + g][kb2 + t2 + 8];
        ql[kc][3] = *(uint32_t*)&sKl[rw + g + 8][kb2 + t2 + 8];
    }

    float m0 = -3.4e38f, m1 = -3.4e38f, l0 = 0.f, l1 = 0.f;
    float o[8][4];
#pragma unroll
    for (int dt = 0; dt < 8; dt++)
#pragma unroll
        for (int i = 0; i < 4; i++) o[dt][i] = 0.f;

    const int NKT = (SS + 63) / 64;   // 17
    for (int kt = 0; kt < NKT; kt++) {
        int k0 = kt * 64;
        __syncthreads();
        // load K (row-major) and V (transposed: d-major) split tiles
#pragma unroll
        for (int j = 0; j < 8; j++) {
            int f = tid + j * 128;
            int row = f >> 4, c4 = f & 15;
            float4 kv = make_float4(0.f,0.f,0.f,0.f);
            float4 vv = make_float4(0.f,0.f,0.f,0.f);
            if (k0 + row < SS) {
                kv = *(const float4*)(Kb + (size_t)(k0 + row) * DH + c4 * 4);
                vv = *(const float4*)(Vb + (size_t)(k0 + row) * DH + c4 * 4);
            }
            __nv_bfloat162 h01 = __floats2bfloat162_rn(kv.x, kv.y);
            __nv_bfloat162 h23 = __floats2bfloat162_rn(kv.z, kv.w);
            __nv_bfloat162 l01 = __floats2bfloat162_rn(kv.x - __bfloat162float(h01.x),
                                                       kv.y - __bfloat162float(h01.y));
            __nv_bfloat162 l23 = __floats2bfloat162_rn(kv.z - __bfloat162float(h23.x),
                                                       kv.w - __bfloat162float(h23.y));
            *(__nv_bfloat162*)&sKh[row][c4*4]     = h01;
            *(__nv_bfloat162*)&sKh[row][c4*4 + 2] = h23;
            *(__nv_bfloat162*)&sKl[row][c4*4]     = l01;
            *(__nv_bfloat162*)&sKl[row][c4*4 + 2] = l23;
            float vf[4] = {vv.x, vv.y, vv.z, vv.w};
#pragma unroll
            for (int u = 0; u < 4; u++) {
                __nv_bfloat16 hh = __float2bfloat16(vf[u]);
                sVh[c4*4 + u][row] = hh;
                sVl[c4*4 + u][row] = __float2bfloat16(vf[u] - __bfloat162float(hh));
            }
        }
        __syncthreads();

        // S = Q @ K^T (16 q x 64 k per warp)
        float s[8][4];
#pragma unroll
        for (int nt = 0; nt < 8; nt++)
#pragma unroll
            for (int i = 0; i < 4; i++) s[nt][i] = 0.f;
#pragma unroll
        for (int kc = 0; kc < 4; kc++) {
            int kb2 = kc * 16;
#pragma unroll
            for (int nt = 0; nt < 8; nt++) {
                int n0 = nt * 8 + g;
                uint32_t bhf[2], blf[2];
                bhf[0] = *(uint32_t*)&sKh[n0][kb2 + t2];
                bhf[1] = *(uint32_t*)&sKh[n0][kb2 + t2 + 8];
                blf[0] = *(uint32_t*)&sKl[n0][kb2 + t2];
                blf[1] = *(uint32_t*)&sKl[n0][kb2 + t2 + 8];
                mma16816(s[nt], qh[kc], bhf);
                mma16816(s[nt], qh[kc], blf);
                mma16816(s[nt], ql[kc], bhf);
            }
        }
        // scale + mask
#pragma unroll
        for (int nt = 0; nt < 8; nt++) {
            int c0v = k0 + nt * 8 + t2, c1v = c0v + 1;
            bool ok0 = c0v < SS, ok1 = c1v < SS;
            s[nt][0] = ok0 ? s[nt][0] * 0.125f : -3.4e38f;
            s[nt][1] = ok1 ? s[nt][1] * 0.125f : -3.4e38f;
            s[nt][2] = ok0 ? s[nt][2] * 0.125f : -3.4e38f;
            s[nt][3] = ok1 ? s[nt][3] * 0.125f : -3.4e38f;
        }
        // online softmax: rows g (regs 0,1) and g+8 (regs 2,3)
        float mx0 = -3.4e38f, mx1 = -3.4e38f;
#pragma unroll
        for (int nt = 0; nt < 8; nt++) {
            mx0 = fmaxf(mx0, fmaxf(s[nt][0], s[nt][1]));
            mx1 = fmaxf(mx1, fmaxf(s[nt][2], s[nt][3]));
        }
        mx0 = fmaxf(mx0, __shfl_xor_sync(0xffffffffu, mx0, 1));
        mx0 = fmaxf(mx0, __shfl_xor_sync(0xffffffffu, mx0, 2));
        mx1 = fmaxf(mx1, __shfl_xor_sync(0xffffffffu, mx1, 1));
        mx1 = fmaxf(mx1, __shfl_xor_sync(0xffffffffu, mx1, 2));
        float nm0 = fmaxf(m0, mx0), nm1 = fmaxf(m1, mx1);
        float cr0 = __expf(m0 - nm0), cr1 = __expf(m1 - nm1);
        float rs0 = 0.f, rs1 = 0.f;
#pragma unroll
        for (int nt = 0; nt < 8; nt++) {
            s[nt][0] = __expf(s[nt][0] - nm0);
            s[nt][1] = __expf(s[nt][1] - nm0);
            s[nt][2] = __expf(s[nt][2] - nm1);
            s[nt][3] = __expf(s[nt][3] - nm1);
            rs0 += s[nt][0] + s[nt][1];
            rs1 += s[nt][2] + s[nt][3];
        }
        rs0 += __shfl_xor_sync(0xffffffffu, rs0, 1);
        rs0 += __shfl_xor_sync(0xffffffffu, rs0, 2);
        rs1 += __shfl_xor_sync(0xffffffffu, rs1, 1);
        rs1 += __shfl_xor_sync(0xffffffffu, rs1, 2);
        l0 = l0 * cr0 + rs0; l1 = l1 * cr1 + rs1;
        m0 = nm0; m1 = nm1;
#pragma unroll
        for (int dt = 0; dt < 8; dt++) {
            o[dt][0] *= cr0; o[dt][1] *= cr0;
            o[dt][2] *= cr1; o[dt][3] *= cr1;
        }
        // repack P (c-frags) -> A-frags with hi/lo split
        uint32_t pah[4][4], pal[4][4];
#pragma unroll
        for (int kc = 0; kc < 4; kc++) {
            int j = kc * 2;
            float p00 = s[j][0],   p01 = s[j][1];
            float p10 = s[j][2],   p11 = s[j][3];
            float p20 = s[j+1][0], p21 = s[j+1][1];
            float p30 = s[j+1][2], p31 = s[j+1][3];
            pah[kc][0] = pack_bf16(p00, p01);
            pah[kc][1] = pack_bf16(p10, p11);
            pah[kc][2] = pack_bf16(p20, p21);
            pah[kc][3] = pack_bf16(p30, p31);
            __nv_bfloat162 t;
            t = *(__nv_bfloat162*)&pah[kc][0];
            pal[kc][0] = pack_bf16(p00 - __bfloat162float(t.x), p01 - __bfloat162float(t.y));
            t = *(__nv_bfloat162*)&pah[kc][1];
            pal[kc][1] = pack_bf16(p10 - __bfloat162float(t.x), p11 - __bfloat162float(t.y));
            t = *(__nv_bfloat162*)&pah[kc][2];
            pal[kc][2] = pack_bf16(p20 - __bfloat162float(t.x), p21 - __bfloat162float(t.y));
            t = *(__nv_bfloat162*)&pah[kc][3];
            pal[kc][3] = pack_bf16(p30 - __bfloat162float(t.x), p31 - __bfloat162float(t.y));
        }
        // O += P @ V  (V^T in smem: sVh[d][key])
#pragma unroll
        for (int kc = 0; kc < 4; kc++) {
            int kb2 = kc * 16;
#pragma unroll
            for (int dt = 0; dt < 8; dt++) {
                int n0 = dt * 8 + g;
                uint32_t bhf[2], blf[2];
                bhf[0] = *(uint32_t*)&sVh[n0][kb2 + t2];
                bhf[1] = *(uint32_t*)&sVh[n0][kb2 + t2 + 8];
                blf[0] = *(uint32_t*)&sVl[n0][kb2 + t2];
                blf[1] = *(uint32_t*)&sVl[n0][kb2 + t2 + 8];
                mma16816(o[dt], pah[kc], bhf);
                mma16816(o[dt], pah[kc], blf);
                mma16816(o[dt], pal[kc], bhf);
            }
        }
    }

    // finalize + fused residual: X += O / l
    float inv0 = 1.f / l0, inv1 = 1.f / l1;
    int q_a = q0 + rw + g, q_b = q0 + rw + g + 8;
#pragma unroll
    for (int dt = 0; dt < 8; dt++) {
        int gc = h * DH + dt * 8 + t2;
        if (q_a < SS) {
            float* xp = g_X + ((size_t)b * SS + q_a) * DM + gc;
            float2 xv = *(float2*)xp;
            xv.x += o[dt][0] * inv0; xv.y += o[dt][1] * inv0;
            *(float2*)xp = xv;
        }
        if (q_b < SS) {
            float* xp = g_X + ((size_t)b * SS + q_b) * DM + gc;
            float2 xv = *(float2*)xp;
            xv.x += o[dt][2] * inv1; xv.y += o[dt][3] * inv1;
            *(float2*)xp = xv;
        }
    }
}

// ---------------- row L2 normalize over DM ----------------
__global__ void norm_k(float* __restrict__ buf)
{
    __shared__ float red[256];
    int tid = threadIdx.x;
    float* p = buf + (size_t)blockIdx.x * DM;
    float v0 = p[tid], v1 = p[tid + 256], v2 = p[tid + 512];
    float ss = blockReduceSum(v0*v0 + v1*v1 + v2*v2, red);
    float inv = 1.f / sqrtf(ss);
    p[tid] = v0 * inv; p[tid + 256] = v1 * inv; p[tid + 512] = v2 * inv;
}

// ---------------- masks: dot(patch, cls) + LN over 19 classes ----------------
__global__ void mask_k(const float* __restrict__ mg, const float* __restrict__ mb)
{
    __shared__ float sp[DM];
    __shared__ float red[128];
    __shared__ float arr[NCLS];
    __shared__ float stats[2];
    int b = blockIdx.y, n = blockIdx.x, tid = threadIdx.x;
    const float* pr = g_PA + ((size_t)b * NTOK + n) * DM;
    for (int i = tid; i < DM; i += 128) sp[i] = pr[i];
    __syncthreads();
    for (int c = 0; c < NCLS; c++) {
        const float* cr = g_CL + ((size_t)b * NCLS + c) * DM;
        float part = 0.f;
        for (int i = tid; i < DM; i += 128) part += sp[i] * cr[i];
        red[tid] = part; __syncthreads();
        for (int s = 64; s > 0; s >>= 1) {
            if (tid < s) red[tid] += red[tid + s];
            __syncthreads();
        }
        if (tid == 0) arr[c] = red[0];
        __syncthreads();
    }
    if (tid == 0) {
        float m = 0.f;
        for (int c = 0; c < NCLS; c++) m += arr[c];
        m *= (1.f / NCLS);
        float v = 0.f;
        for (int c = 0; c < NCLS; c++) { float d = arr[c] - m; v += d * d; }
        v *= (1.f / NCLS);
        stats[0] = m;
        stats[1] = rsqrtf(v + 1e-5f);
    }
    __syncthreads();
    if (tid < NCLS) {
        float val = (arr[tid] - stats[0]) * stats[1] * mg[tid] + mb[tid];
        g_MS[((size_t)b * NCLS + tid) * NTOK + n] = val;
    }
}

// ---------------- bilinear 32x32 -> 512x512 ----------------
__global__ void resize_k(float* __restrict__ out)
{
    size_t idx = (size_t)blockIdx.x * 256 + threadIdx.x;
    if (idx >= (size_t)BB * NCLS * IMG * IMG) return;
    int x = (int)(idx & (IMG - 1));
    int y = (int)((idx >> 9) & (IMG - 1));
    int bc = (int)(idx >> 18);
    float fy = (y + 0.5f) * 0.0625f - 0.5f;
    float fx = (x + 0.5f) * 0.0625f - 0.5f;
    int y0 = (int)floorf(fy); float wy = fy - (float)y0;
    int x0 = (int)floorf(fx); float wx = fx - (float)x0;
    int y0c = max(y0, 0), y1c = min(y0 + 1, GSZ - 1);
    int x0c = max(x0, 0), x1c = min(x0 + 1, GSZ - 1);
    const float* mp = g_MS + (size_t)bc * NTOK;
    float v00 = mp[y0c * GSZ + x0c], v01 = mp[y0c * GSZ + x1c];
    float v10 = mp[y1c * GSZ + x0c], v11 = mp[y1c * GSZ + x1c];
    out[idx] = (1.f - wy) * ((1.f - wx) * v00 + wx * v01)
             +        wy  * ((1.f - wx) * v10 + wx * v11);
}

// ---------------- launch ----------------
extern "C" void kernel_launch(void* const* d_in, const int* in_sizes, int n_in,
                              void* d_out, int out_size)
{
    const float* x          = (const float*)d_in[0];
    const float* proj_dec_W = (const float*)d_in[1];
    const float* proj_dec_b = (const float*)d_in[2];
    const float* cls_emb    = (const float*)d_in[3];
    const float* ln1_g      = (const float*)d_in[4];
    const float* ln1_b      = (const float*)d_in[5];
    const float* qW         = (const float*)d_in[6];
    const float* qb         = (const float*)d_in[7];
    const float* kW         = (const float*)d_in[8];
    const float* kb         = (const float*)d_in[9];
    const float* vW         = (const float*)d_in[10];
    const float* vb         = (const float*)d_in[11];
    const float* ln2_g      = (const float*)d_in[12];
    const float* ln2_b      = (const float*)d_in[13];
    const float* mlp_W1     = (const float*)d_in[14];
    const float* mlp_b1     = (const float*)d_in[15];
    const float* mlp_W2     = (const float*)d_in[16];
    const float* mlp_b2     = (const float*)d_in[17];
    const float* proj_patch = (const float*)d_in[18];
    const float* proj_cls   = (const float*)d_in[19];
    const float* dec_g      = (const float*)d_in[20];
    const float* dec_b      = (const float*)d_in[21];
    const float* mask_g     = (const float*)d_in[22];
    const float* mask_b     = (const float*)d_in[23];

    float *X, *Hb, *FF, *PA, *CL;
    __nv_bfloat16 *Wh, *Wl;
    cudaGetSymbolAddress((void**)&X,  g_X);
    cudaGetSymbolAddress((void**)&Hb, g_Hb);
    cudaGetSymbolAddress((void**)&FF, g_FF);
    cudaGetSymbolAddress((void**)&PA, g_PA);
    cudaGetSymbolAddress((void**)&CL, g_CL);
    cudaGetSymbolAddress((void**)&Wh, g_Wh);
    cudaGetSymbolAddress((void**)&Wl, g_Wl);

    const int Mtok = BB * NTOK;  // 8192
    const int Mall = BB * SS;    // 8344
    dim3 wb(32, 8);

    // weight transpose + split (cheap, every launch)
    wsplit_k<<<dim3(24, 24), wb>>>(proj_dec_W, Wh + OFF_PD, Wl + OFF_PD, 768, 768);
    wsplit_k<<<dim3(24, 24), wb>>>(proj_patch, Wh + OFF_PP, Wl + OFF_PP, 768, 768);
    for (int l = 0; l < 2; l++) {
        wsplit_k<<<dim3(96, 24), wb>>>(mlp_W1 + (size_t)l*DM*DFF, Wh + OFF_M1(l), Wl + OFF_M1(l), 768, 3072);
        wsplit_k<<<dim3(24, 96), wb>>>(mlp_W2 + (size_t)l*DFF*DM, Wh + OFF_M2(l), Wl + OFF_M2(l), 3072, 768);
    }

    // x @ proj_dec_W + b -> X (ragged rows)
    gemm_mma<false><<<dim3(6, 64), 256>>>(
        x, Wh + OFF_PD, Wl + OFF_PD, proj_dec_b, nullptr, X, Mtok, DM, DM, 0, 0, NTOK, SS);
    cls_copy_k<<<(BB*NCLS*DM + 255)/256, 256>>>(cls_emb);

    for (int l = 0; l < 2; l++) {
        ln_k<<<Mall, 256>>>(X, ln1_g + l*DM, ln1_b + l*DM, Hb);
        qkv_k<<<dim3((SS + 63)/64, NH, BB*3), 256>>>(qW, qb, kW, kb, vW, vb, l);
        flash_mma_k<<<dim3((SS + 63)/64, BB*NH), 128>>>();   // fused X += O
        ln_k<<<Mall, 256>>>(X, ln2_g + l*DM, ln2_b + l*DM, Hb);
        gemm_mma<true><<<dim3(24, 66), 256>>>(
            Hb, Wh + OFF_M1(l), Wl + OFF_M1(l), mlp_b1 + l*DFF, nullptr, FF,
            Mall, DFF, DM, 0, 0, 0, 0);
        gemm_mma<false><<<dim3(6, 66), 256>>>(
            FF, Wh + OFF_M2(l), Wl + OFF_M2(l), mlp_b2 + l*DM, X, X,
            Mall, DM, DFF, 0, 0, 0, 0);
    }

    ln_k<<<Mall, 256>>>(X, dec_g, dec_b, Hb);
    gemm_mma<false><<<dim3(6, 64), 256>>>(
        Hb, Wh + OFF_PP, Wl + OFF_PP, nullptr, nullptr, PA, Mtok, DM, DM, NTOK, SS, 0, 0);
    sgemm_k<false><<<dim3(DM/128, (BB*NCLS + 127)/128), 256>>>(
        Hb + (size_t)NTOK*DM, proj_cls, nullptr, nullptr, CL, BB*NCLS, DM, DM, NCLS, SS, 0, 0);
    norm_k<<<Mtok, 256>>>(PA);
    norm_k<<<BB*NCLS, 256>>>(CL);
    mask_k<<<dim3(NTOK, BB), 128>>>(mask_g, mask_b);
    resize_k<<<(int)(((size_t)BB*NCLS*IMG*IMG + 255)/256), 256>>>((float*)d_out);
}